// round 17
// baseline (speedup 1.0000x reference)
#include <cuda_runtime.h>
#include <cuda_fp16.h>
#include <math.h>
#include <stdint.h>

#define B_ 4
#define T_ 4096
#define D_ 1024
#define H_ 8
#define K_ 128
#define V_ 128
#define F_ 4096
#define M_ (B_*T_)   // 16384 rows
#define NTC 32       // recurrence timesteps per smem chunk

// ---------------- scratch (device globals) ----------------
__device__ __align__(128) __half g_nh[(size_t)M_*D_];
__device__ __align__(128) __half g_qkvh[(size_t)M_*3*D_];
__device__ __align__(128) __half g_qh[(size_t)M_*H_*K_];
__device__ __align__(128) __half g_kh[(size_t)M_*H_*K_];
__device__ __align__(128) __half g_vh[(size_t)M_*H_*V_];
__device__ __align__(128) float g_al[(size_t)B_*H_*T_];   // transposed [B*H, T]
__device__ __align__(128) float g_be[(size_t)B_*H_*T_];
__device__ __align__(128) __half g_oh[(size_t)M_*H_*V_];
__device__ __align__(128) float g_x1[(size_t)M_*D_];
__device__ __align__(128) __half g_hh[(size_t)M_*D_];
__device__ __align__(128) __half g_fh[(size_t)M_*F_];
__device__ __align__(128) __half g_wqkv[(size_t)3*1024*1024];
__device__ __align__(128) __half g_wo[1024*1024];
__device__ __align__(128) __half g_w1[(size_t)4096*1024];
__device__ __align__(128) __half g_w2[(size_t)1024*4096];

// ======================== PTX helpers ========================
__device__ __forceinline__ uint32_t smem_u32(const void* p) {
    uint32_t a;
    asm("{ .reg .u64 t; cvta.to.shared.u64 t, %1; cvt.u32.u64 %0, t; }" : "=r"(a) : "l"(p));
    return a;
}
__device__ __forceinline__ void cp16(uint32_t s, const void* g) {
    asm volatile("cp.async.cg.shared.global [%0], [%1], 16;\n" :: "r"(s), "l"(g));
}
__device__ __forceinline__ void cp_commit() { asm volatile("cp.async.commit_group;\n" ::: "memory"); }
template<int N> __device__ __forceinline__ void cp_wait() {
    asm volatile("cp.async.wait_group %0;\n" :: "n"(N) : "memory");
}
__device__ __forceinline__ void ldsm4(uint32_t& r0, uint32_t& r1, uint32_t& r2, uint32_t& r3, uint32_t addr) {
    asm volatile("ldmatrix.sync.aligned.m8n8.x4.shared.b16 {%0,%1,%2,%3}, [%4];"
        : "=r"(r0), "=r"(r1), "=r"(r2), "=r"(r3) : "r"(addr));
}
__device__ __forceinline__ void mma16816(float* d, const uint32_t* a, const uint32_t* b) {
    asm volatile("mma.sync.aligned.m16n8k16.row.col.f32.f16.f16.f32 "
        "{%0,%1,%2,%3},{%4,%5,%6,%7},{%8,%9},{%0,%1,%2,%3};"
        : "+f"(d[0]), "+f"(d[1]), "+f"(d[2]), "+f"(d[3])
        : "r"(a[0]), "r"(a[1]), "r"(a[2]), "r"(a[3]), "r"(b[0]), "r"(b[1]));
}
__device__ __forceinline__ float silu_f(float x) {
    return x / (1.f + __expf(-x));
}

// ======================== HMMA GEMM (R13-proven) ========================
// 128x128x32 tiles, 8 warps (4m x 2n), warp tile 32x64.
// 4-stage cp.async ring, lookahead 2, ONE barrier per chunk.
// EPI: 0=fp32, 1=+resid fp32, 2=+bias+GELU->fp16, 3=+bias+resid fp32, 6=fp16
#define ROWB 80
#define ARR_B (128*ROWB)
#define STG_B (2*ARR_B)
#define NSTAGE 4
#define DSMEM_SZ (NSTAGE*STG_B + 1024)

template<int EPI>
__global__ __launch_bounds__(256, 2) void tc_gemm(
    const __half* __restrict__ A, const __half* __restrict__ Bw,
    const float* __restrict__ bias, const float* __restrict__ resid,
    float* __restrict__ C, __half* __restrict__ Ch,
    int M, int N, int Kd)
{
    extern __shared__ __align__(1024) char dsm_raw[];
    const int tid = threadIdx.x;
    const int wid = tid >> 5, lane = tid & 31;
    const int row0 = blockIdx.y * 128;
    const int col0 = blockIdx.x * 128;
    const int NC = Kd >> 5;

    uint32_t sbase = smem_u32(dsm_raw);
    sbase = (sbase + 1023) & ~1023u;

    const int wm0 = (wid >> 1) * 32;
    const int wn0 = (wid & 1) * 64;

    float acc[2][8][4];
    #pragma unroll
    for (int i = 0; i < 2; i++)
        #pragma unroll
        for (int j = 0; j < 8; j++)
            #pragma unroll
            for (int r = 0; r < 4; r++) acc[i][j][r] = 0.f;

    auto load_chunk = [&](int c) {
        const int kb = c << 5;
        const uint32_t sb = sbase + (c % NSTAGE) * STG_B;
        #pragma unroll
        for (int arr = 0; arr < 2; arr++) {
            const __half* src = (arr == 0) ? A : Bw;
            const int rb = (arr == 0) ? row0 : col0;
            #pragma unroll
            for (int i2 = 0; i2 < 2; i2++) {
                int idx = tid + i2 * 256;
                int row = idx >> 2, seg = idx & 3;
                cp16(sb + arr * ARR_B + row * ROWB + seg * 16,
                     src + (size_t)(rb + row) * Kd + kb + seg * 8);
            }
        }
        cp_commit();
    };

    load_chunk(0);
    load_chunk(1);

    const int sub = lane >> 3, r8 = lane & 7;

    for (int c = 0; c < NC; c++) {
        if (c + 2 < NC) { load_chunk(c + 2); cp_wait<2>(); }
        else if (c + 1 < NC) cp_wait<1>();
        else cp_wait<0>();
        __syncthreads();

        const uint32_t sb = sbase + (c % NSTAGE) * STG_B;
        #pragma unroll
        for (int kk = 0; kk < 2; kk++) {
            const int kbyte = kk * 32;
            uint32_t af[2][4];
            #pragma unroll
            for (int mi = 0; mi < 2; mi++) {
                int row = wm0 + mi * 16 + (sub & 1) * 8 + r8;
                uint32_t off = row * ROWB + kbyte + (sub >> 1) * 16;
                ldsm4(af[mi][0], af[mi][1], af[mi][2], af[mi][3], sb + off);
            }
            uint32_t bf[8][2];
            #pragma unroll
            for (int nj = 0; nj < 4; nj++) {
                int row = wn0 + nj * 16 + (sub >> 1) * 8 + r8;
                uint32_t off = row * ROWB + kbyte + (sub & 1) * 16;
                ldsm4(bf[nj*2][0], bf[nj*2][1], bf[nj*2+1][0], bf[nj*2+1][1], sb + ARR_B + off);
            }
            #pragma unroll
            for (int mi = 0; mi < 2; mi++)
                #pragma unroll
                for (int ni = 0; ni < 8; ni++)
                    mma16816(acc[mi][ni], af[mi], bf[ni]);
        }
    }

    const int bcol0 = col0 + wn0;
    float2 bv[8];
    if (EPI == 2 || EPI == 3) {
        #pragma unroll
        for (int ni = 0; ni < 8; ni++)
            bv[ni] = *(const float2*)(bias + bcol0 + ni * 8 + (lane & 3) * 2);
    }
    #pragma unroll
    for (int mi = 0; mi < 2; mi++) {
        #pragma unroll
        for (int hf = 0; hf < 2; hf++) {
            const int row = row0 + wm0 + mi * 16 + hf * 8 + (lane >> 2);
            #pragma unroll
            for (int ni = 0; ni < 8; ni++) {
                const int col = bcol0 + ni * 8 + (lane & 3) * 2;
                float y0 = acc[mi][ni][hf*2];
                float y1 = acc[mi][ni][hf*2+1];
                if (EPI == 2 || EPI == 3) { y0 += bv[ni].x; y1 += bv[ni].y; }
                if (EPI == 2) {
                    y0 = 0.5f*y0*(1.f + erff(y0*0.70710678118f));
                    y1 = 0.5f*y1*(1.f + erff(y1*0.70710678118f));
                }
                if (EPI == 1 || EPI == 3) {
                    float2 rv = *(const float2*)(resid + (size_t)row * N + col);
                    y0 += rv.x; y1 += rv.y;
                }
                if (EPI == 2 || EPI == 6) {
                    __half2 hh(__float2half_rn(y0), __float2half_rn(y1));
                    *(uint32_t*)(Ch + (size_t)row * N + col) = *(uint32_t*)&hh;
                } else {
                    *(float2*)(C + (size_t)row * N + col) = make_float2(y0, y1);
                }
            }
        }
    }
}

// ---------------- LayerNorm -> fp16 ----------------
__global__ __launch_bounds__(256) void ln_kernel(const float* __restrict__ x,
    const float* __restrict__ w, const float* __restrict__ bb,
    __half* __restrict__ oh)
{
    __shared__ float rs[8], rs2[8];
    int row = blockIdx.x, tid = threadIdx.x;
    const float4* xr = (const float4*)(x + (size_t)row * D_);
    float4 v = xr[tid];
    float s  = v.x + v.y + v.z + v.w;
    float s2 = v.x*v.x + v.y*v.y + v.z*v.z + v.w*v.w;
    #pragma unroll
    for (int m = 16; m; m >>= 1) {
        s  += __shfl_xor_sync(~0u, s,  m);
        s2 += __shfl_xor_sync(~0u, s2, m);
    }
    if ((tid & 31) == 0) { rs[tid>>5] = s; rs2[tid>>5] = s2; }
    __syncthreads();
    s = 0.f; s2 = 0.f;
    #pragma unroll
    for (int i = 0; i < 8; i++) { s += rs[i]; s2 += rs2[i]; }
    float mean = s * (1.0f/D_);
    float var  = s2 * (1.0f/D_) - mean*mean;
    float inv  = rsqrtf(var + 1e-5f);
    float4 wv = ((const float4*)w)[tid];
    float4 bv = ((const float4*)bb)[tid];
    float o0 = (v.x-mean)*inv*wv.x + bv.x;
    float o1 = (v.y-mean)*inv*wv.y + bv.y;
    float o2 = (v.z-mean)*inv*wv.z + bv.z;
    float o3 = (v.w-mean)*inv*wv.w + bv.w;
    __half2 h0(__float2half_rn(o0), __float2half_rn(o1));
    __half2 h1(__float2half_rn(o2), __float2half_rn(o3));
    ((uint2*)(oh + (size_t)row * D_))[tid] = make_uint2(*(uint32_t*)&h0, *(uint32_t*)&h1);
}

// ---------------- weight transpose ----------------
__global__ __launch_bounds__(256) void wconvT(const float* __restrict__ W,
    __half* __restrict__ WT, int Kd, int N)
{
    __shared__ float t[32][33];
    int n0 = blockIdx.x * 32, k0 = blockIdx.y * 32;
    int tx = threadIdx.x & 31, ty = threadIdx.x >> 5;
    #pragma unroll
    for (int i = 0; i < 4; i++)
        t[ty + 8*i][tx] = W[(size_t)(k0 + ty + 8*i) * N + n0 + tx];
    __syncthreads();
    #pragma unroll
    for (int i = 0; i < 4; i++)
        WT[(size_t)(n0 + ty + 8*i) * Kd + k0 + tx] = __float2half_rn(t[tx][ty + 8*i]);
}

__global__ __launch_bounds__(256) void wconvT3(const float* __restrict__ Wq,
    const float* __restrict__ Wk, const float* __restrict__ Wv,
    __half* __restrict__ WT)
{
    __shared__ float t[32][33];
    const float* W = (blockIdx.z == 0) ? Wq : (blockIdx.z == 1) ? Wk : Wv;
    __half* dst = WT + (size_t)blockIdx.z * 1024 * 1024;
    int n0 = blockIdx.x * 32, k0 = blockIdx.y * 32;
    int tx = threadIdx.x & 31, ty = threadIdx.x >> 5;
    #pragma unroll
    for (int i = 0; i < 4; i++)
        t[ty + 8*i][tx] = W[(size_t)(k0 + ty + 8*i) * 1024 + n0 + tx];
    __syncthreads();
    #pragma unroll
    for (int i = 0; i < 4; i++)
        dst[(size_t)(n0 + ty + 8*i) * 1024 + k0 + tx] = __float2half_rn(t[tx][ty + 8*i]);
}

// ---------------- alpha/beta -> transposed [B*H, T], smem row staging --------
__global__ __launch_bounds__(128) void ab_kernel(const __half* __restrict__ n,
    const float* __restrict__ Wb, const float* __restrict__ Wa,
    float* __restrict__ alT, float* __restrict__ beT)
{
    __shared__ float srow[1024];
    int row = blockIdx.x, tid = threadIdx.x;     // row = b*T + t
    // stage the row once: 128 threads x 8 halves
    {
        uint4 hv = ((const uint4*)(n + (size_t)row * D_))[tid];
        const __half2* hp = (const __half2*)&hv;
        float4* dst = (float4*)&srow[tid * 8];
        float2 f0 = __half22float2(hp[0]);
        float2 f1 = __half22float2(hp[1]);
        float2 f2 = __half22float2(hp[2]);
        float2 f3 = __half22float2(hp[3]);
        dst[0] = make_float4(f0.x, f0.y, f1.x, f1.y);
        dst[1] = make_float4(f2.x, f2.y, f3.x, f3.y);
    }
    __syncthreads();
    int g = tid >> 3, l = tid & 7;
    const float* W = (g < 8) ? Wb : Wa;
    int c = g & 7;
    float s = 0.f;
    for (int d = l; d < D_; d += 8) s = fmaf(srow[d], W[d*H_ + c], s);
    s += __shfl_xor_sync(~0u, s, 1);
    s += __shfl_xor_sync(~0u, s, 2);
    s += __shfl_xor_sync(~0u, s, 4);
    if (l == 0) {
        float sig = 1.f/(1.f + __expf(-s));
        int b = row >> 12, t = row & (T_ - 1);
        size_t oidx = ((size_t)(b * H_ + c)) * T_ + t;
        if (g < 8) beT[oidx] = sig;
        else       alT[oidx] = sig;
    }
}

// ---------------- silu + l2norm on q,k; silu on v (fp16 in) -> fp16 ----------
__global__ __launch_bounds__(128) void act_qkv_kernel(const __half* __restrict__ qkv,
    __half* __restrict__ q, __half* __restrict__ kk, __half* __restrict__ v)
{
    __shared__ float rq[4], rk[4];
    int row = blockIdx.x, tid = threadIdx.x;
    int m = row >> 3, h = row & 7;
    const __half* src = qkv + (size_t)m * 3072 + h * 128;
    float xq = __half2float(src[tid]);
    float xk = __half2float(src[1024 + tid]);
    float xv = __half2float(src[2048 + tid]);
    float yq = silu_f(xq);
    float yk = silu_f(xk);
    float sq = yq*yq, sk2 = yk*yk;
    #pragma unroll
    for (int mm = 16; mm; mm >>= 1) {
        sq  += __shfl_xor_sync(~0u, sq,  mm);
        sk2 += __shfl_xor_sync(~0u, sk2, mm);
    }
    if ((tid & 31) == 0) { rq[tid>>5] = sq; rk[tid>>5] = sk2; }
    __syncthreads();
    float nq = rq[0]+rq[1]+rq[2]+rq[3];
    float nk = rk[0]+rk[1]+rk[2]+rk[3];
    size_t idx = (size_t)row*128 + tid;
    q[idx]  = __float2half(yq * rsqrtf(nq + 1e-6f));
    kk[idx] = __float2half(yk * rsqrtf(nk + 1e-6f));
    v[idx]  = __float2half(silu_f(xv));
}

// ---------------- gated delta-rule recurrence (chunked, 256 threads) ----------
// 256 blocks: bh = blk>>3, split = blk&7 (16 V-cols). 256 threads:
// col = tid>>4 (16 cols), r16 = tid&15 (8 state rows each). 16-lane reductions.
// ~3.5 warps/SMSP with co-residency -> stall hiding.
__global__ __launch_bounds__(256) void recur_kernel(
    const __half* __restrict__ q, const __half* __restrict__ k, const __half* __restrict__ v,
    const float* __restrict__ alT, const float* __restrict__ beT, __half* __restrict__ o)
{
    __shared__ __align__(16) __half sk[2][NTC*128];
    __shared__ __align__(16) __half sq[2][NTC*128];
    __shared__ __align__(16) __half sv[2][NTC*16];
    __shared__ __align__(16) float sa[2][NTC];
    __shared__ __align__(16) float sb_[2][NTC];

    const int blk = blockIdx.x;
    const int bh = blk >> 3, split = blk & 7;
    const int b = bh >> 3, h = bh & 7;
    const int tid = threadIdx.x;
    const int col = tid >> 4, r16 = tid & 15;
    const size_t base = ((size_t)b * T_ * H_ + h) * (size_t)K_;
    const size_t abbase = (size_t)bh * T_;

    auto load_chunk = [&](int c, int d) {
        const char* kc = (const char*)(k + base + (size_t)c * NTC * (H_*K_));
        const char* qc = (const char*)(q + base + (size_t)c * NTC * (H_*K_));
        const char* vc = (const char*)(v + base + (size_t)c * NTC * (H_*K_) + split*16);
        uint32_t skb = smem_u32(&sk[d][0]);
        uint32_t sqb = smem_u32(&sq[d][0]);
        #pragma unroll
        for (int i = 0; i < 2; i++) {
            int idx = tid + i * 256;         // 0..511
            int row = idx >> 4, seg = idx & 15;
            cp16(skb + row*256 + seg*16, kc + (size_t)row*2048 + seg*16);
            cp16(sqb + row*256 + seg*16, qc + (size_t)row*2048 + seg*16);
        }
        if (tid < 64) {
            int row = tid >> 1, seg = tid & 1;
            cp16(smem_u32(&sv[d][0]) + row*32 + seg*16, vc + (size_t)row*2048 + seg*16);
        } else if (tid < 72) {
            int s = tid - 64;
            cp16(smem_u32(&sa[d][0]) + s*16, (const char*)(alT + abbase + c*NTC) + s*16);
        } else if (tid < 80) {
            int s = tid - 72;
            cp16(smem_u32(&sb_[d][0]) + s*16, (const char*)(beT + abbase + c*NTC) + s*16);
        }
        cp_commit();
    };

    float S[8];
    #pragma unroll
    for (int i = 0; i < 8; i++) S[i] = 0.f;

    const int NCH = T_ / NTC;   // 128
    load_chunk(0, 0);

    for (int c = 0; c < NCH; c++) {
        const int d = c & 1;
        if (c + 1 < NCH) { load_chunk(c + 1, d ^ 1); cp_wait<1>(); }
        else cp_wait<0>();
        __syncthreads();

        const char* skd = (const char*)&sk[d][0] + r16 * 16;
        const char* sqd = (const char*)&sq[d][0] + r16 * 16;

        #pragma unroll 2
        for (int tt = 0; tt < NTC; tt++) {
            float a  = sa[d][tt], bt = sb_[d][tt];
            float vv = __half2float(sv[d][tt*16 + col]);

            uint4 k0 = *(const uint4*)(skd + tt*256);
            float kreg[8];
            {
                const __half2* hp = (const __half2*)&k0;
                #pragma unroll
                for (int j = 0; j < 4; j++) {
                    float2 f = __half22float2(hp[j]);
                    kreg[2*j] = f.x; kreg[2*j+1] = f.y;
                }
            }
            float kv0 = 0.f, kv1 = 0.f, kv2 = 0.f, kv3 = 0.f;
            #pragma unroll
            for (int i = 0; i < 2; i++) {
                kv0 = fmaf(kreg[4*i+0], S[4*i+0], kv0);
                kv1 = fmaf(kreg[4*i+1], S[4*i+1], kv1);
                kv2 = fmaf(kreg[4*i+2], S[4*i+2], kv2);
                kv3 = fmaf(kreg[4*i+3], S[4*i+3], kv3);
            }
            float kv = (kv0+kv1)+(kv2+kv3);
            kv += __shfl_xor_sync(~0u, kv, 1);
            kv += __shfl_xor_sync(~0u, kv, 2);
            kv += __shfl_xor_sync(~0u, kv, 4);
            kv += __shfl_xor_sync(~0u, kv, 8);

            float w = bt * (vv - a * kv);
            #pragma unroll
            for (int i = 0; i < 8; i++) S[i] = fmaf(a, S[i], kreg[i]*w);

            uint4 q0 = *(const uint4*)(sqd + tt*256);
            float o0 = 0.f, o1 = 0.f, o2 = 0.f, o3 = 0.f;
            {
                const __half2* hp = (const __half2*)&q0;
                #pragma unroll
                for (int j = 0; j < 2; j++) {
                    float2 f0 = __half22float2(hp[2*j]);
                    float2 f1 = __half22float2(hp[2*j+1]);
                    o0 = fmaf(f0.x, S[4*j+0], o0);
                    o1 = fmaf(f0.y, S[4*j+1], o1);
                    o2 = fmaf(f1.x, S[4*j+2], o2);
                    o3 = fmaf(f1.y, S[4*j+3], o3);
                }
            }
            float oa = (o0+o1)+(o2+o3);
            oa += __shfl_xor_sync(~0u, oa, 1);
            oa += __shfl_xor_sync(~0u, oa, 2);
            oa += __shfl_xor_sync(~0u, oa, 4);
            oa += __shfl_xor_sync(~0u, oa, 8);
            if (r16 == 0)
                o[base + (size_t)(c*NTC + tt)*(H_*K_) + split*16 + col] = __float2half(oa);
        }
        __syncthreads();
    }
}

// ---------------- launch ----------------
extern "C" void kernel_launch(void* const* d_in, const int* in_sizes, int n_in,
                              void* d_out, int out_size)
{
    const float* x    = (const float*)d_in[0];
    const float* Wq   = (const float*)d_in[1];
    const float* Wk   = (const float*)d_in[2];
    const float* Wv   = (const float*)d_in[3];
    const float* Wb   = (const float*)d_in[4];
    const float* Wa   = (const float*)d_in[5];
    const float* Wo   = (const float*)d_in[6];
    const float* ln1w = (const float*)d_in[7];
    const float* ln1b = (const float*)d_in[8];
    const float* ln2w = (const float*)d_in[9];
    const float* ln2b = (const float*)d_in[10];
    const float* W1   = (const float*)d_in[11];
    const float* b1   = (const float*)d_in[12];
    const float* W2   = (const float*)d_in[13];
    const float* b2   = (const float*)d_in[14];
    float* out = (float*)d_out;

    float *al_, *be_, *x1_;
    __half *nh, *qkvh, *qh, *kh, *vh, *oh, *hh, *fh, *wqkv, *wo, *w1, *w2;
    cudaGetSymbolAddress((void**)&nh,   g_nh);
    cudaGetSymbolAddress((void**)&qkvh, g_qkvh);
    cudaGetSymbolAddress((void**)&qh,   g_qh);
    cudaGetSymbolAddress((void**)&kh,   g_kh);
    cudaGetSymbolAddress((void**)&vh,   g_vh);
    cudaGetSymbolAddress((void**)&al_,  g_al);
    cudaGetSymbolAddress((void**)&be_,  g_be);
    cudaGetSymbolAddress((void**)&oh,   g_oh);
    cudaGetSymbolAddress((void**)&x1_,  g_x1);
    cudaGetSymbolAddress((void**)&hh,   g_hh);
    cudaGetSymbolAddress((void**)&fh,   g_fh);
    cudaGetSymbolAddress((void**)&wqkv, g_wqkv);
    cudaGetSymbolAddress((void**)&wo,   g_wo);
    cudaGetSymbolAddress((void**)&w1,   g_w1);
    cudaGetSymbolAddress((void**)&w2,   g_w2);

    cudaFuncSetAttribute(tc_gemm<1>, cudaFuncAttributeMaxDynamicSharedMemorySize, DSMEM_SZ);
    cudaFuncSetAttribute(tc_gemm<2>, cudaFuncAttributeMaxDynamicSharedMemorySize, DSMEM_SZ);
    cudaFuncSetAttribute(tc_gemm<3>, cudaFuncAttributeMaxDynamicSharedMemorySize, DSMEM_SZ);
    cudaFuncSetAttribute(tc_gemm<6>, cudaFuncAttributeMaxDynamicSharedMemorySize, DSMEM_SZ);

    ln_kernel<<<M_, 256>>>(x, ln1w, ln1b, nh);                               // 0
    wconvT3<<<dim3(32, 32, 3), 256>>>(Wq, Wk, Wv, wqkv);                     // 1
    ab_kernel<<<M_, 128>>>(nh, Wb, Wa, al_, be_);                            // 2

    dim3 gqkv(3072/128, M_/128);
    tc_gemm<6><<<gqkv, 256, DSMEM_SZ>>>(nh, wqkv, nullptr, nullptr, nullptr, qkvh, M_, 3072, 1024); // 3 <- PROFILED

    act_qkv_kernel<<<M_*H_, 128>>>(qkvh, qh, kh, vh);                        // 4

    recur_kernel<<<B_*H_*8, 256>>>(qh, kh, vh, al_, be_, oh);                // 5

    wconvT<<<dim3(1024/32, 1024/32), 256>>>(Wo, wo, 1024, 1024);             // 6

    dim3 g1(1024/128, M_/128);
    tc_gemm<1><<<g1, 256, DSMEM_SZ>>>(oh, wo, nullptr, x, x1_, nullptr, M_, 1024, 1024); // 7

    ln_kernel<<<M_, 256>>>(x1_, ln2w, ln2b, hh);                             // 8

    wconvT<<<dim3(4096/32, 1024/32), 256>>>(W1, w1, 1024, 4096);             // 9
    wconvT<<<dim3(1024/32, 4096/32), 256>>>(W2, w2, 4096, 1024);             // 10

    dim3 g2(4096/128, M_/128);
    tc_gemm<2><<<g2, 256, DSMEM_SZ>>>(hh, w1, b1, nullptr, nullptr, fh, M_, 4096, 1024); // 11
    tc_gemm<3><<<g1, 256, DSMEM_SZ>>>(fh, w2, b2, x1_, out, nullptr, M_, 1024, 4096);    // 12
}